// round 16
// baseline (speedup 1.0000x reference)
#include <cuda_runtime.h>
#include <cstdint>

#define NHEADS 16
#define HID    1024
#define TT     2048
#define BB     32

typedef unsigned long long ull;

// ---------------- device scratch (no allocations allowed) ----------------
__device__ float g_wqh[NHEADS * HID];                 // tf32-hi of folded q @ kv_w
__device__ float g_wql[NHEADS * HID];                 // tf32-lo residual
__device__ float g_c[NHEADS];
__device__ float g_logits[BB * NHEADS * TT];          // logits -> attn tf32-hi (in place)
__device__ float g_attnl[BB * NHEADS * TT];           // attn tf32-lo residual
__device__ float g_pooled[BB * NHEADS * HID];         // pooled hidden
__device__ float g_outv[BB * HID];

static __device__ __forceinline__ unsigned smaddr(const void* p) {
    return (unsigned)__cvta_generic_to_shared(p);
}
#define CP16(dst, src)  asm volatile("cp.async.cg.shared.global [%0], [%1], 16;" :: "r"(dst), "l"(src))
#define CP_COMMIT()     asm volatile("cp.async.commit_group;" ::: "memory")
#define CP_WAIT1()      asm volatile("cp.async.wait_group 1;" ::: "memory")
#define CP_WAIT2()      asm volatile("cp.async.wait_group 2;" ::: "memory")

static __device__ __forceinline__ unsigned cvt_tf32(float x) {
    unsigned r;
    asm("cvt.rna.tf32.f32 %0, %1;" : "=r"(r) : "f"(x));
    return r;
}
#define MMA8(d0, d1, d2, d3, a0, a1, a2, a3, b0, b1)                     \
    asm("mma.sync.aligned.m16n8k8.row.col.f32.tf32.tf32.f32 "            \
        "{%0,%1,%2,%3},{%4,%5,%6,%7},{%8,%9},{%0,%1,%2,%3};"             \
        : "+f"(d0), "+f"(d1), "+f"(d2), "+f"(d3)                         \
        : "r"(a0), "r"(a1), "r"(a2), "r"(a3), "r"(b0), "r"(b1))

// ---------------- kernel 1: fold query into kv_w (k half), emit tf32 hi/lo ----------------
__global__ void k_wq(const float* __restrict__ q,
                     const float* __restrict__ kvw,
                     const float* __restrict__ kvb) {
    int w = blockIdx.x * (blockDim.x >> 5) + (threadIdx.x >> 5);
    int lane = threadIdx.x & 31;
    if (w < NHEADS * HID) {
        int h = w & (NHEADS - 1);
        int i = w >> 4;
        const float* wr = kvw + (size_t)i * (2 * HID) + h * 64;
        const float* qr = q + h * 64;
        float s = qr[lane] * wr[lane] + qr[lane + 32] * wr[lane + 32];
        #pragma unroll
        for (int o = 16; o; o >>= 1) s += __shfl_xor_sync(0xffffffffu, s, o);
        if (lane == 0) {
            float v = 0.125f * s;
            unsigned hi = cvt_tf32(v);
            g_wqh[h * HID + i] = __uint_as_float(hi);
            g_wql[h * HID + i] = __uint_as_float(cvt_tf32(v - __uint_as_float(hi)));
        }
    }
    if (blockIdx.x == 0 && threadIdx.x < NHEADS) {
        int h = threadIdx.x;
        float s = 0.f;
        for (int d = 0; d < 64; d++) s += q[h * 64 + d] * kvb[h * 64 + d];
        g_c[h] = 0.125f * s;
    }
}

// ---------------- kernel 2: logits via tensor cores (measured-best R14/R11) ----------------
#define LCH 16
#define HP  20
__global__ void __launch_bounds__(256) k_logits(const float* __restrict__ hid) {
    extern __shared__ __align__(16) float hsm[];        // [3][256][20]
    __shared__ __align__(16) float wq_s[3][2][NHEADS][HP];
    int tid = threadIdx.x;
    int wid = tid >> 5, l = tid & 31;
    int grp = l >> 2,   thr = l & 3;
    const float* hblk = hid + (size_t)blockIdx.x * 256 * HID;

    float acc[2][2][4];
    #pragma unroll
    for (int m = 0; m < 2; m++)
        #pragma unroll
        for (int n = 0; n < 2; n++)
            #pragma unroll
            for (int r = 0; r < 4; r++) acc[m][n][r] = 0.f;

    #define LFILL(st, kc)                                                          \
        do {                                                                       \
            _Pragma("unroll")                                                      \
            for (int p = 0; p < 4; p++) {                                          \
                int idx = p * 256 + tid;                                           \
                int row = idx >> 2;                                                \
                int q4  = (idx & 3) * 4;                                           \
                CP16(smaddr(hsm + ((st) * 256 + row) * HP + q4),                   \
                     hblk + (size_t)row * HID + (kc) + q4);                        \
            }                                                                      \
            if (tid < 128) {                                                       \
                int half = tid >> 6;                                               \
                int hh   = (tid >> 2) & 15;                                        \
                int kq   = (tid & 3) * 4;                                          \
                const float* src = half ? g_wql : g_wqh;                           \
                CP16(smaddr(&wq_s[st][half][hh][kq]), src + hh * HID + (kc) + kq); \
            }                                                                      \
        } while (0)

    LFILL(0, 0);   CP_COMMIT();
    LFILL(1, LCH); CP_COMMIT();

    for (int c = 0; c < HID / LCH; c++) {
        if (c + 2 < HID / LCH) {
            int st = (c + 2) % 3;
            int kc = (c + 2) * LCH;
            LFILL(st, kc);
        }
        CP_COMMIT();
        CP_WAIT2();
        __syncthreads();

        int buf = c % 3;
        const float*    hs = hsm + buf * 256 * HP;
        const unsigned* wh = (const unsigned*)&wq_s[buf][0][0][0];
        const unsigned* wl = (const unsigned*)&wq_s[buf][1][0][0];

        #pragma unroll
        for (int s = 0; s < 2; s++) {
            int k0 = s * 8;
            unsigned b0h0 = wh[(grp)     * HP + k0 + thr];
            unsigned b1h0 = wh[(grp)     * HP + k0 + thr + 4];
            unsigned b0h1 = wh[(8 + grp) * HP + k0 + thr];
            unsigned b1h1 = wh[(8 + grp) * HP + k0 + thr + 4];
            unsigned b0l0 = wl[(grp)     * HP + k0 + thr];
            unsigned b1l0 = wl[(grp)     * HP + k0 + thr + 4];
            unsigned b0l1 = wl[(8 + grp) * HP + k0 + thr];
            unsigned b1l1 = wl[(8 + grp) * HP + k0 + thr + 4];
            #pragma unroll
            for (int m = 0; m < 2; m++) {
                int jb = wid * 32 + m * 16;
                unsigned a0 = cvt_tf32(hs[(jb + grp)     * HP + k0 + thr]);
                unsigned a1 = cvt_tf32(hs[(jb + grp + 8) * HP + k0 + thr]);
                unsigned a2 = cvt_tf32(hs[(jb + grp)     * HP + k0 + thr + 4]);
                unsigned a3 = cvt_tf32(hs[(jb + grp + 8) * HP + k0 + thr + 4]);
                MMA8(acc[m][0][0], acc[m][0][1], acc[m][0][2], acc[m][0][3],
                     a0, a1, a2, a3, b0h0, b1h0);
                MMA8(acc[m][0][0], acc[m][0][1], acc[m][0][2], acc[m][0][3],
                     a0, a1, a2, a3, b0l0, b1l0);
                MMA8(acc[m][1][0], acc[m][1][1], acc[m][1][2], acc[m][1][3],
                     a0, a1, a2, a3, b0h1, b1h1);
                MMA8(acc[m][1][0], acc[m][1][1], acc[m][1][2], acc[m][1][3],
                     a0, a1, a2, a3, b0l1, b1l1);
            }
        }
        __syncthreads();
    }

    int jg = blockIdx.x * 256 + wid * 32;
    int b  = jg >> 11;
    #pragma unroll
    for (int m = 0; m < 2; m++) {
        int j0 = (jg + m * 16 + grp) & 2047;
        #pragma unroll
        for (int n = 0; n < 2; n++) {
            int h0 = n * 8 + 2 * thr;
            g_logits[((size_t)(b * NHEADS + h0))     * TT + j0]     = acc[m][n][0] + g_c[h0];
            g_logits[((size_t)(b * NHEADS + h0 + 1)) * TT + j0]     = acc[m][n][1] + g_c[h0 + 1];
            g_logits[((size_t)(b * NHEADS + h0))     * TT + j0 + 8] = acc[m][n][2] + g_c[h0];
            g_logits[((size_t)(b * NHEADS + h0 + 1)) * TT + j0 + 8] = acc[m][n][3] + g_c[h0 + 1];
        }
    }
}

// ---------------- kernel 3: softmax -> attn tf32 hi (in place) + lo ----------------
__global__ void __launch_bounds__(256) k_softmax(const int* __restrict__ mask) {
    int bh = blockIdx.x;
    int b  = bh >> 4;
    float* row = g_logits + (size_t)bh * TT;
    float* rowl = g_attnl + (size_t)bh * TT;
    const int* mrow = mask + (size_t)b * TT;
    int tid = threadIdx.x;

    float x[8];
    float mx = -1e30f;
    #pragma unroll
    for (int r = 0; r < 8; r++) {
        int j = tid + r * 256;
        float v = row[j];
        if (mrow[j] == 0) v = -1e30f;
        x[r] = v;
        mx = fmaxf(mx, v);
    }
    __shared__ float red[8];
    #pragma unroll
    for (int o = 16; o; o >>= 1) mx = fmaxf(mx, __shfl_xor_sync(0xffffffffu, mx, o));
    if ((tid & 31) == 0) red[tid >> 5] = mx;
    __syncthreads();
    mx = red[0];
    #pragma unroll
    for (int w = 1; w < 8; w++) mx = fmaxf(mx, red[w]);

    float sum = 0.f;
    #pragma unroll
    for (int r = 0; r < 8; r++) { float e = __expf(x[r] - mx); x[r] = e; sum += e; }
    #pragma unroll
    for (int o = 16; o; o >>= 1) sum += __shfl_xor_sync(0xffffffffu, sum, o);
    __syncthreads();
    if ((tid & 31) == 0) red[tid >> 5] = sum;
    __syncthreads();
    sum = red[0] + red[1] + red[2] + red[3] + red[4] + red[5] + red[6] + red[7];
    float inv = __fdividef(1.f, sum);
    #pragma unroll
    for (int r = 0; r < 8; r++) {
        int j = tid + r * 256;
        float w = x[r] * inv;
        unsigned hi = cvt_tf32(w);
        row[j]  = __uint_as_float(hi);
        rowl[j] = __uint_as_float(cvt_tf32(w - __uint_as_float(hi)));
    }
}

// ---------------- kernel 4: pool via tensor cores (measured-best R14) ----------------
#define PBP 136
#define PAP 36
#define HID3 (3 * 32 * PBP)                 // 13056 floats
#define AH0  HID3                           // attn-hi stages
#define AL0  (HID3 + 3 * NHEADS * PAP)      // attn-lo stages
__global__ void __launch_bounds__(256) k_pool(const float* __restrict__ hid) {
    extern __shared__ __align__(16) float psm[];
    int b   = blockIdx.y;
    int i0  = blockIdx.x * 128;
    int tid = threadIdx.x;
    int wid = tid >> 5, l = tid & 31;
    int grp = l >> 2,   thr = l & 3;

    const float* hbase = hid + (size_t)b * TT * HID + i0;

    #define PFILL(st, j0)                                                          \
        do {                                                                       \
            _Pragma("unroll")                                                      \
            for (int p = 0; p < 4; p++) {                                          \
                int idx = p * 256 + tid;                                           \
                int row = idx >> 5;                                                \
                int c4  = (idx & 31) * 4;                                          \
                CP16(smaddr(psm + (st) * 32 * PBP + row * PBP + c4),               \
                     hbase + (size_t)((j0) + row) * HID + c4);                     \
            }                                                                      \
            {                                                                      \
                int half = tid >> 7;                                               \
                int hh   = (tid >> 3) & 15;                                        \
                int j4   = (tid & 7) * 4;                                          \
                const float* src = half ? g_attnl : g_logits;                      \
                int base = half ? AL0 : AH0;                                       \
                CP16(smaddr(psm + base + (st) * NHEADS * PAP + hh * PAP + j4),     \
                     src + ((size_t)(b * NHEADS + hh)) * TT + (j0) + j4);          \
            }                                                                      \
        } while (0)

    float acc[2][4];
    #pragma unroll
    for (int n = 0; n < 2; n++)
        #pragma unroll
        for (int r = 0; r < 4; r++) acc[n][r] = 0.f;

    PFILL(0, 0);  CP_COMMIT();
    PFILL(1, 32); CP_COMMIT();

    for (int s = 0; s < 64; s++) {
        CP_WAIT1();
        __syncthreads();
        if (s + 2 < 64) PFILL((s + 2) % 3, (s + 2) * 32);
        CP_COMMIT();

        int buf = s % 3;
        const float*    hs = psm + buf * 32 * PBP;
        const unsigned* ah = (const unsigned*)(psm + AH0 + buf * NHEADS * PAP);
        const unsigned* al = (const unsigned*)(psm + AL0 + buf * NHEADS * PAP);

        #pragma unroll
        for (int ks = 0; ks < 4; ks++) {
            int k0 = ks * 8;
            unsigned a0h = ah[(grp)     * PAP + k0 + thr];
            unsigned a1h = ah[(grp + 8) * PAP + k0 + thr];
            unsigned a2h = ah[(grp)     * PAP + k0 + thr + 4];
            unsigned a3h = ah[(grp + 8) * PAP + k0 + thr + 4];
            unsigned a0l = al[(grp)     * PAP + k0 + thr];
            unsigned a1l = al[(grp + 8) * PAP + k0 + thr];
            unsigned a2l = al[(grp)     * PAP + k0 + thr + 4];
            unsigned a3l = al[(grp + 8) * PAP + k0 + thr + 4];
            #pragma unroll
            for (int n = 0; n < 2; n++) {
                int ib = wid * 16 + n * 8 + grp;
                unsigned b0h = cvt_tf32(hs[(k0 + thr)     * PBP + ib]);
                unsigned b1h = cvt_tf32(hs[(k0 + thr + 4) * PBP + ib]);
                MMA8(acc[n][0], acc[n][1], acc[n][2], acc[n][3],
                     a0h, a1h, a2h, a3h, b0h, b1h);
                MMA8(acc[n][0], acc[n][1], acc[n][2], acc[n][3],
                     a0l, a1l, a2l, a3l, b0h, b1h);
            }
        }
    }

    #pragma unroll
    for (int n = 0; n < 2; n++) {
        int i = i0 + wid * 16 + n * 8 + 2 * thr;
        *(float2*)(g_pooled + ((size_t)(b * NHEADS + grp))     * HID + i) =
            make_float2(acc[n][0], acc[n][1]);
        *(float2*)(g_pooled + ((size_t)(b * NHEADS + grp + 8)) * HID + i) =
            make_float2(acc[n][2], acc[n][3]);
    }
}

// ---------------- kernel 5: per-head V projection with weight-tile reuse ----------------
__global__ void __launch_bounds__(256) k_vproj(const float* __restrict__ kvw,
                                               const float* __restrict__ kvb) {
    int h  = blockIdx.x;
    int dg = blockIdx.y;
    __shared__ float p_s[32][64];
    __shared__ float w_s[64 * 32];
    int tid = threadIdx.x;
    int d   = tid & 31;
    int bg  = tid >> 5;

    float acc[4] = {0.f, 0.f, 0.f, 0.f};

    for (int c = 0; c < 16; c++) {
        int i0 = c * 64;
        __syncthreads();
        #pragma unroll
        for (int p = 0; p < 2; p++) {
            int o4 = (p * 256 + tid) * 4;
            int i  = o4 >> 5;
            int cc = o4 & 31;
            *(float4*)&w_s[o4] =
                *(const float4*)(kvw + (size_t)(i0 + i) * (2 * HID) + HID + h * 64 + dg * 32 + cc);
        }
        #pragma unroll
        for (int p = 0; p < 2; p++) {
            int idx = p * 256 + tid;
            int b   = idx >> 4;
            int c4  = (idx & 15) * 4;
            *(float4*)&p_s[b][c4] =
                *(const float4*)(g_pooled + ((size_t)b * NHEADS + h) * HID + i0 + c4);
        }
        __syncthreads();

        #pragma unroll 8
        for (int i = 0; i < 64; i++) {
            float w = w_s[i * 32 + d];
            #pragma unroll
            for (int bb = 0; bb < 4; bb++)
                acc[bb] += p_s[bg * 4 + bb][i] * w;
        }
    }

    float bias = kvb[HID + h * 64 + dg * 32 + d];
    #pragma unroll
    for (int bb = 0; bb < 4; bb++) {
        int b = bg * 4 + bb;
        g_outv[b * HID + h * 64 + dg * 32 + d] = acc[bb] + bias;
    }
}

// ---------------- kernel 6: fused final GEMM [32,1024]x[1024,1024] + bias -> out ----------------
// 32 blocks, each owns a 32-wide p-slice and loops all 1024 c in 64-chunks.
// outw read exactly once (broadcast across warps); no partials, no 2nd kernel.
__global__ void __launch_bounds__(256) k_final(const float* __restrict__ outw,
                                               const float* __restrict__ outb,
                                               float* __restrict__ out) {
    int p0 = blockIdx.x * 32;
    __shared__ float outv_s[32][64];
    int tid = threadIdx.x;
    int d   = tid & 31;
    int bg  = tid >> 5;             // 8 warps, 4 b each

    float acc[4] = {0.f, 0.f, 0.f, 0.f};

    for (int c0 = 0; c0 < HID; c0 += 64) {
        __syncthreads();
        #pragma unroll
        for (int p = 0; p < 2; p++) {
            int idx = p * 256 + tid;
            int b   = idx >> 4;
            int c4  = (idx & 15) * 4;
            *(float4*)&outv_s[b][c4] = *(const float4*)(g_outv + b * HID + c0 + c4);
        }
        __syncthreads();

        #pragma unroll 8
        for (int cc = 0; cc < 64; cc++) {
            float w = __ldg(outw + (size_t)(c0 + cc) * 1024 + p0 + d);
            #pragma unroll
            for (int bb = 0; bb < 4; bb++)
                acc[bb] += outv_s[bg * 4 + bb][cc] * w;
        }
    }

    float bias = outb[p0 + d];
    #pragma unroll
    for (int bb = 0; bb < 4; bb++) {
        int b = bg * 4 + bb;
        out[(size_t)b * 1024 + p0 + d] = acc[bb] + bias;
    }
}

// ---------------- launch ----------------
extern "C" void kernel_launch(void* const* d_in, const int* in_sizes, int n_in,
                              void* d_out, int out_size) {
    const float* hid  = (const float*)d_in[0];
    const int*   mask = (const int*)  d_in[1];
    const float* kvw  = (const float*)d_in[2];
    const float* kvb  = (const float*)d_in[3];
    const float* outw = (const float*)d_in[4];
    const float* outb = (const float*)d_in[5];
    const float* q    = (const float*)d_in[6];
    float* out = (float*)d_out;

    cudaFuncSetAttribute(k_logits, cudaFuncAttributeMaxDynamicSharedMemorySize, 61440);
    cudaFuncSetAttribute(k_pool,   cudaFuncAttributeMaxDynamicSharedMemorySize, 66048);

    k_wq     <<<2048, 256>>>(q, kvw, kvb);
    k_logits <<<256, 256, 61440>>>(hid);
    k_softmax<<<512, 256>>>(mask);
    k_pool   <<<dim3(8, 32), 256, 66048>>>(hid);
    k_vproj  <<<dim3(16, 2), 256>>>(kvw, kvb);
    k_final  <<<32, 256>>>(outw, outb, out);
}

// round 17
// speedup vs baseline: 2.0679x; 2.0679x over previous
#include <cuda_runtime.h>
#include <cstdint>

#define NHEADS 16
#define HID    1024
#define TT     2048
#define BB     32

typedef unsigned long long ull;

// ---------------- device scratch (no allocations allowed) ----------------
__device__ float g_wqh[NHEADS * HID];                 // tf32-hi of folded q @ kv_w
__device__ float g_wql[NHEADS * HID];                 // tf32-lo residual
__device__ float g_c[NHEADS];
__device__ float g_logits[BB * NHEADS * TT];          // logits -> attn tf32-hi (in place)
__device__ float g_attnl[BB * NHEADS * TT];           // attn tf32-lo residual
__device__ float g_pooled[BB * NHEADS * HID];         // pooled hidden
__device__ float g_outvp[4 * BB * HID];               // v-proj partials (4 i-slices)
__device__ float g_fpart[16 * BB * HID];

static __device__ __forceinline__ unsigned smaddr(const void* p) {
    return (unsigned)__cvta_generic_to_shared(p);
}
#define CP16(dst, src)  asm volatile("cp.async.cg.shared.global [%0], [%1], 16;" :: "r"(dst), "l"(src))
#define CP_COMMIT()     asm volatile("cp.async.commit_group;" ::: "memory")
#define CP_WAIT1()      asm volatile("cp.async.wait_group 1;" ::: "memory")
#define CP_WAIT2()      asm volatile("cp.async.wait_group 2;" ::: "memory")

static __device__ __forceinline__ unsigned cvt_tf32(float x) {
    unsigned r;
    asm("cvt.rna.tf32.f32 %0, %1;" : "=r"(r) : "f"(x));
    return r;
}
#define MMA8(d0, d1, d2, d3, a0, a1, a2, a3, b0, b1)                     \
    asm("mma.sync.aligned.m16n8k8.row.col.f32.tf32.tf32.f32 "            \
        "{%0,%1,%2,%3},{%4,%5,%6,%7},{%8,%9},{%0,%1,%2,%3};"             \
        : "+f"(d0), "+f"(d1), "+f"(d2), "+f"(d3)                         \
        : "r"(a0), "r"(a1), "r"(a2), "r"(a3), "r"(b0), "r"(b1))

// ---------------- kernel 1: fold query into kv_w (k half), emit tf32 hi/lo ----------------
__global__ void k_wq(const float* __restrict__ q,
                     const float* __restrict__ kvw,
                     const float* __restrict__ kvb) {
    int w = blockIdx.x * (blockDim.x >> 5) + (threadIdx.x >> 5);
    int lane = threadIdx.x & 31;
    if (w < NHEADS * HID) {
        int h = w & (NHEADS - 1);
        int i = w >> 4;
        const float* wr = kvw + (size_t)i * (2 * HID) + h * 64;
        const float* qr = q + h * 64;
        float s = qr[lane] * wr[lane] + qr[lane + 32] * wr[lane + 32];
        #pragma unroll
        for (int o = 16; o; o >>= 1) s += __shfl_xor_sync(0xffffffffu, s, o);
        if (lane == 0) {
            float v = 0.125f * s;
            unsigned hi = cvt_tf32(v);
            g_wqh[h * HID + i] = __uint_as_float(hi);
            g_wql[h * HID + i] = __uint_as_float(cvt_tf32(v - __uint_as_float(hi)));
        }
    }
    if (blockIdx.x == 0 && threadIdx.x < NHEADS) {
        int h = threadIdx.x;
        float s = 0.f;
        for (int d = 0; d < 64; d++) s += q[h * 64 + d] * kvb[h * 64 + d];
        g_c[h] = 0.125f * s;
    }
}

// ---------------- kernel 2: logits via tensor cores (measured-best R14/R11) ----------------
#define LCH 16
#define HP  20
__global__ void __launch_bounds__(256) k_logits(const float* __restrict__ hid) {
    extern __shared__ __align__(16) float hsm[];        // [3][256][20]
    __shared__ __align__(16) float wq_s[3][2][NHEADS][HP];
    int tid = threadIdx.x;
    int wid = tid >> 5, l = tid & 31;
    int grp = l >> 2,   thr = l & 3;
    const float* hblk = hid + (size_t)blockIdx.x * 256 * HID;

    float acc[2][2][4];
    #pragma unroll
    for (int m = 0; m < 2; m++)
        #pragma unroll
        for (int n = 0; n < 2; n++)
            #pragma unroll
            for (int r = 0; r < 4; r++) acc[m][n][r] = 0.f;

    #define LFILL(st, kc)                                                          \
        do {                                                                       \
            _Pragma("unroll")                                                      \
            for (int p = 0; p < 4; p++) {                                          \
                int idx = p * 256 + tid;                                           \
                int row = idx >> 2;                                                \
                int q4  = (idx & 3) * 4;                                           \
                CP16(smaddr(hsm + ((st) * 256 + row) * HP + q4),                   \
                     hblk + (size_t)row * HID + (kc) + q4);                        \
            }                                                                      \
            if (tid < 128) {                                                       \
                int half = tid >> 6;                                               \
                int hh   = (tid >> 2) & 15;                                        \
                int kq   = (tid & 3) * 4;                                          \
                const float* src = half ? g_wql : g_wqh;                           \
                CP16(smaddr(&wq_s[st][half][hh][kq]), src + hh * HID + (kc) + kq); \
            }                                                                      \
        } while (0)

    LFILL(0, 0);   CP_COMMIT();
    LFILL(1, LCH); CP_COMMIT();

    for (int c = 0; c < HID / LCH; c++) {
        if (c + 2 < HID / LCH) {
            int st = (c + 2) % 3;
            int kc = (c + 2) * LCH;
            LFILL(st, kc);
        }
        CP_COMMIT();
        CP_WAIT2();
        __syncthreads();

        int buf = c % 3;
        const float*    hs = hsm + buf * 256 * HP;
        const unsigned* wh = (const unsigned*)&wq_s[buf][0][0][0];
        const unsigned* wl = (const unsigned*)&wq_s[buf][1][0][0];

        #pragma unroll
        for (int s = 0; s < 2; s++) {
            int k0 = s * 8;
            unsigned b0h0 = wh[(grp)     * HP + k0 + thr];
            unsigned b1h0 = wh[(grp)     * HP + k0 + thr + 4];
            unsigned b0h1 = wh[(8 + grp) * HP + k0 + thr];
            unsigned b1h1 = wh[(8 + grp) * HP + k0 + thr + 4];
            unsigned b0l0 = wl[(grp)     * HP + k0 + thr];
            unsigned b1l0 = wl[(grp)     * HP + k0 + thr + 4];
            unsigned b0l1 = wl[(8 + grp) * HP + k0 + thr];
            unsigned b1l1 = wl[(8 + grp) * HP + k0 + thr + 4];
            #pragma unroll
            for (int m = 0; m < 2; m++) {
                int jb = wid * 32 + m * 16;
                unsigned a0 = cvt_tf32(hs[(jb + grp)     * HP + k0 + thr]);
                unsigned a1 = cvt_tf32(hs[(jb + grp + 8) * HP + k0 + thr]);
                unsigned a2 = cvt_tf32(hs[(jb + grp)     * HP + k0 + thr + 4]);
                unsigned a3 = cvt_tf32(hs[(jb + grp + 8) * HP + k0 + thr + 4]);
                MMA8(acc[m][0][0], acc[m][0][1], acc[m][0][2], acc[m][0][3],
                     a0, a1, a2, a3, b0h0, b1h0);
                MMA8(acc[m][0][0], acc[m][0][1], acc[m][0][2], acc[m][0][3],
                     a0, a1, a2, a3, b0l0, b1l0);
                MMA8(acc[m][1][0], acc[m][1][1], acc[m][1][2], acc[m][1][3],
                     a0, a1, a2, a3, b0h1, b1h1);
                MMA8(acc[m][1][0], acc[m][1][1], acc[m][1][2], acc[m][1][3],
                     a0, a1, a2, a3, b0l1, b1l1);
            }
        }
        __syncthreads();
    }

    int jg = blockIdx.x * 256 + wid * 32;
    int b  = jg >> 11;
    #pragma unroll
    for (int m = 0; m < 2; m++) {
        int j0 = (jg + m * 16 + grp) & 2047;
        #pragma unroll
        for (int n = 0; n < 2; n++) {
            int h0 = n * 8 + 2 * thr;
            g_logits[((size_t)(b * NHEADS + h0))     * TT + j0]     = acc[m][n][0] + g_c[h0];
            g_logits[((size_t)(b * NHEADS + h0 + 1)) * TT + j0]     = acc[m][n][1] + g_c[h0 + 1];
            g_logits[((size_t)(b * NHEADS + h0))     * TT + j0 + 8] = acc[m][n][2] + g_c[h0];
            g_logits[((size_t)(b * NHEADS + h0 + 1)) * TT + j0 + 8] = acc[m][n][3] + g_c[h0 + 1];
        }
    }
}

// ---------------- kernel 3: softmax -> attn tf32 hi (in place) + lo ----------------
__global__ void __launch_bounds__(256) k_softmax(const int* __restrict__ mask) {
    int bh = blockIdx.x;
    int b  = bh >> 4;
    float* row = g_logits + (size_t)bh * TT;
    float* rowl = g_attnl + (size_t)bh * TT;
    const int* mrow = mask + (size_t)b * TT;
    int tid = threadIdx.x;

    float x[8];
    float mx = -1e30f;
    #pragma unroll
    for (int r = 0; r < 8; r++) {
        int j = tid + r * 256;
        float v = row[j];
        if (mrow[j] == 0) v = -1e30f;
        x[r] = v;
        mx = fmaxf(mx, v);
    }
    __shared__ float red[8];
    #pragma unroll
    for (int o = 16; o; o >>= 1) mx = fmaxf(mx, __shfl_xor_sync(0xffffffffu, mx, o));
    if ((tid & 31) == 0) red[tid >> 5] = mx;
    __syncthreads();
    mx = red[0];
    #pragma unroll
    for (int w = 1; w < 8; w++) mx = fmaxf(mx, red[w]);

    float sum = 0.f;
    #pragma unroll
    for (int r = 0; r < 8; r++) { float e = __expf(x[r] - mx); x[r] = e; sum += e; }
    #pragma unroll
    for (int o = 16; o; o >>= 1) sum += __shfl_xor_sync(0xffffffffu, sum, o);
    __syncthreads();
    if ((tid & 31) == 0) red[tid >> 5] = sum;
    __syncthreads();
    sum = red[0] + red[1] + red[2] + red[3] + red[4] + red[5] + red[6] + red[7];
    float inv = __fdividef(1.f, sum);
    #pragma unroll
    for (int r = 0; r < 8; r++) {
        int j = tid + r * 256;
        float w = x[r] * inv;
        unsigned hi = cvt_tf32(w);
        row[j]  = __uint_as_float(hi);
        rowl[j] = __uint_as_float(cvt_tf32(w - __uint_as_float(hi)));
    }
}

// ---------------- kernel 4: pool via tensor cores (measured-best R14) ----------------
#define PBP 136
#define PAP 36
#define HID3 (3 * 32 * PBP)                 // 13056 floats
#define AH0  HID3                           // attn-hi stages
#define AL0  (HID3 + 3 * NHEADS * PAP)      // attn-lo stages
__global__ void __launch_bounds__(256) k_pool(const float* __restrict__ hid) {
    extern __shared__ __align__(16) float psm[];
    int b   = blockIdx.y;
    int i0  = blockIdx.x * 128;
    int tid = threadIdx.x;
    int wid = tid >> 5, l = tid & 31;
    int grp = l >> 2,   thr = l & 3;

    const float* hbase = hid + (size_t)b * TT * HID + i0;

    #define PFILL(st, j0)                                                          \
        do {                                                                       \
            _Pragma("unroll")                                                      \
            for (int p = 0; p < 4; p++) {                                          \
                int idx = p * 256 + tid;                                           \
                int row = idx >> 5;                                                \
                int c4  = (idx & 31) * 4;                                          \
                CP16(smaddr(psm + (st) * 32 * PBP + row * PBP + c4),               \
                     hbase + (size_t)((j0) + row) * HID + c4);                     \
            }                                                                      \
            {                                                                      \
                int half = tid >> 7;                                               \
                int hh   = (tid >> 3) & 15;                                        \
                int j4   = (tid & 7) * 4;                                          \
                const float* src = half ? g_attnl : g_logits;                      \
                int base = half ? AL0 : AH0;                                       \
                CP16(smaddr(psm + base + (st) * NHEADS * PAP + hh * PAP + j4),     \
                     src + ((size_t)(b * NHEADS + hh)) * TT + (j0) + j4);          \
            }                                                                      \
        } while (0)

    float acc[2][4];
    #pragma unroll
    for (int n = 0; n < 2; n++)
        #pragma unroll
        for (int r = 0; r < 4; r++) acc[n][r] = 0.f;

    PFILL(0, 0);  CP_COMMIT();
    PFILL(1, 32); CP_COMMIT();

    for (int s = 0; s < 64; s++) {
        CP_WAIT1();
        __syncthreads();
        if (s + 2 < 64) PFILL((s + 2) % 3, (s + 2) * 32);
        CP_COMMIT();

        int buf = s % 3;
        const float*    hs = psm + buf * 32 * PBP;
        const unsigned* ah = (const unsigned*)(psm + AH0 + buf * NHEADS * PAP);
        const unsigned* al = (const unsigned*)(psm + AL0 + buf * NHEADS * PAP);

        #pragma unroll
        for (int ks = 0; ks < 4; ks++) {
            int k0 = ks * 8;
            unsigned a0h = ah[(grp)     * PAP + k0 + thr];
            unsigned a1h = ah[(grp + 8) * PAP + k0 + thr];
            unsigned a2h = ah[(grp)     * PAP + k0 + thr + 4];
            unsigned a3h = ah[(grp + 8) * PAP + k0 + thr + 4];
            unsigned a0l = al[(grp)     * PAP + k0 + thr];
            unsigned a1l = al[(grp + 8) * PAP + k0 + thr];
            unsigned a2l = al[(grp)     * PAP + k0 + thr + 4];
            unsigned a3l = al[(grp + 8) * PAP + k0 + thr + 4];
            #pragma unroll
            for (int n = 0; n < 2; n++) {
                int ib = wid * 16 + n * 8 + grp;
                unsigned b0h = cvt_tf32(hs[(k0 + thr)     * PBP + ib]);
                unsigned b1h = cvt_tf32(hs[(k0 + thr + 4) * PBP + ib]);
                MMA8(acc[n][0], acc[n][1], acc[n][2], acc[n][3],
                     a0h, a1h, a2h, a3h, b0h, b1h);
                MMA8(acc[n][0], acc[n][1], acc[n][2], acc[n][3],
                     a0l, a1l, a2l, a3l, b0h, b1h);
            }
        }
    }

    #pragma unroll
    for (int n = 0; n < 2; n++) {
        int i = i0 + wid * 16 + n * 8 + 2 * thr;
        *(float2*)(g_pooled + ((size_t)(b * NHEADS + grp))     * HID + i) =
            make_float2(acc[n][0], acc[n][1]);
        *(float2*)(g_pooled + ((size_t)(b * NHEADS + grp + 8)) * HID + i) =
            make_float2(acc[n][2], acc[n][3]);
    }
}

// ---------------- kernel 5: per-head V projection, 4-way i-split (128 blocks) ----------------
// block = (h, dg, cs): partial over i in [cs*256, cs*256+256). No bias here;
// bias + 4-way sum folded into k_final staging.
__global__ void __launch_bounds__(256) k_vproj(const float* __restrict__ kvw) {
    int h  = blockIdx.x;
    int dg = blockIdx.y;
    int cs = blockIdx.z;            // 0..3
    __shared__ float p_s[32][64];
    __shared__ float w_s[64 * 32];
    int tid = threadIdx.x;
    int d   = tid & 31;
    int bg  = tid >> 5;

    float acc[4] = {0.f, 0.f, 0.f, 0.f};

    for (int c = 0; c < 4; c++) {
        int i0 = cs * 256 + c * 64;
        __syncthreads();
        #pragma unroll
        for (int p = 0; p < 2; p++) {
            int o4 = (p * 256 + tid) * 4;
            int i  = o4 >> 5;
            int cc = o4 & 31;
            *(float4*)&w_s[o4] =
                *(const float4*)(kvw + (size_t)(i0 + i) * (2 * HID) + HID + h * 64 + dg * 32 + cc);
        }
        #pragma unroll
        for (int p = 0; p < 2; p++) {
            int idx = p * 256 + tid;
            int b   = idx >> 4;
            int c4  = (idx & 15) * 4;
            *(float4*)&p_s[b][c4] =
                *(const float4*)(g_pooled + ((size_t)b * NHEADS + h) * HID + i0 + c4);
        }
        __syncthreads();

        #pragma unroll 8
        for (int i = 0; i < 64; i++) {
            float w = w_s[i * 32 + d];
            #pragma unroll
            for (int bb = 0; bb < 4; bb++)
                acc[bb] += p_s[bg * 4 + bb][i] * w;
        }
    }

    #pragma unroll
    for (int bb = 0; bb < 4; bb++) {
        int b = bg * 4 + bb;
        g_outvp[((size_t)cs * BB + b) * HID + h * 64 + dg * 32 + d] = acc[bb];
    }
}

// ---------------- kernel 6: final GEMM (R14-measured shape), vproj reduce folded in ----------------
__global__ void __launch_bounds__(256) k_final(const float* __restrict__ outw,
                                               const float* __restrict__ kvb) {
    int p0 = blockIdx.x * 128;
    int c0 = blockIdx.y * 64;
    __shared__ float outv_s[32][64];
    int tid = threadIdx.x;
    for (int t = tid; t < 32 * 16; t += 256) {
        int bb2 = t >> 4;
        int c4  = (t & 15) * 4;
        float4 s  = *(const float4*)(g_outvp + ((size_t)0 * BB + bb2) * HID + c0 + c4);
        float4 v1 = *(const float4*)(g_outvp + ((size_t)1 * BB + bb2) * HID + c0 + c4);
        float4 v2 = *(const float4*)(g_outvp + ((size_t)2 * BB + bb2) * HID + c0 + c4);
        float4 v3 = *(const float4*)(g_outvp + ((size_t)3 * BB + bb2) * HID + c0 + c4);
        float4 bi = *(const float4*)(kvb + HID + c0 + c4);
        s.x += v1.x + v2.x + v3.x + bi.x;
        s.y += v1.y + v2.y + v3.y + bi.y;
        s.z += v1.z + v2.z + v3.z + bi.z;
        s.w += v1.w + v2.w + v3.w + bi.w;
        *(float4*)&outv_s[bb2][c4] = s;
    }
    __syncthreads();

    int p   = tid & 127;
    int bh2 = tid >> 7;
    float acc[16];
    #pragma unroll
    for (int n = 0; n < 16; n++) acc[n] = 0.f;

    #pragma unroll 4
    for (int cc = 0; cc < 64; cc++) {
        float w = __ldg(outw + (size_t)(c0 + cc) * 1024 + p0 + p);
        #pragma unroll
        for (int n = 0; n < 16; n++) acc[n] += outv_s[bh2 * 16 + n][cc] * w;
    }
    #pragma unroll
    for (int n = 0; n < 16; n++)
        g_fpart[((size_t)blockIdx.y * BB + bh2 * 16 + n) * 1024 + p0 + p] = acc[n];
}

__global__ void k_finred(const float* __restrict__ outb, float* __restrict__ out) {
    int idx = blockIdx.x * 256 + threadIdx.x;
    int b = idx >> 10;
    int p = idx & 1023;
    float s = outb[p];
    #pragma unroll
    for (int cs = 0; cs < 16; cs++) s += g_fpart[((size_t)cs * BB + b) * 1024 + p];
    out[idx] = s;
}

// ---------------- launch ----------------
extern "C" void kernel_launch(void* const* d_in, const int* in_sizes, int n_in,
                              void* d_out, int out_size) {
    const float* hid  = (const float*)d_in[0];
    const int*   mask = (const int*)  d_in[1];
    const float* kvw  = (const float*)d_in[2];
    const float* kvb  = (const float*)d_in[3];
    const float* outw = (const float*)d_in[4];
    const float* outb = (const float*)d_in[5];
    const float* q    = (const float*)d_in[6];
    float* out = (float*)d_out;

    cudaFuncSetAttribute(k_logits, cudaFuncAttributeMaxDynamicSharedMemorySize, 61440);
    cudaFuncSetAttribute(k_pool,   cudaFuncAttributeMaxDynamicSharedMemorySize, 66048);

    k_wq     <<<2048, 256>>>(q, kvw, kvb);
    k_logits <<<256, 256, 61440>>>(hid);
    k_softmax<<<512, 256>>>(mask);
    k_pool   <<<dim3(8, 32), 256, 66048>>>(hid);
    k_vproj  <<<dim3(16, 2, 4), 256>>>(kvw);
    k_final  <<<dim3(8, 16), 256>>>(outw, kvb);
    k_finred <<<128, 256>>>(outb, out);
}